// round 4
// baseline (speedup 1.0000x reference)
#include <cuda_runtime.h>
#include <math.h>
#include <stdint.h>

// ============================================================================
// TPForth: e3nn-style tensor product, B x (x1[156], x2[9], w[7128]) -> out[156]
// Persistent kernel: 148 blocks (1/SM), 320 threads, 3-stage TMA pipeline.
// Each stage holds 2 rows' weights (57KB) + x1 (1.2KB). DRAM never drains.
// ============================================================================

#define WTOT 7128
#define XW   156
#define STAGES 3
#define STAGE_W_BYTES  (2 * WTOT * 4)   // 57024
#define STAGE_X1_BYTES (2 * XW * 4)     // 1248
#define STAGE_BYTES    (STAGE_W_BYTES + STAGE_X1_BYTES)

// Weight sub-matrix offsets (floats within a row), shapes (U, Wd):
//  w00  @    0 (48,48)   w01  @ 2304 (48,10)   w10  @ 2784 (10,10)
//  w110 @ 2884 (10,48)   w112 @ 3364 (10,10)   w12  @ 3464 (10,10)
//  w20  @ 3564 (10,10)   w211 @ 3664 (10,10)   w213 @ 3764 (10,48)
//  w22  @ 4244 (10,10)   w30  @ 4344 (48,48)   w31  @ 6648 (48,10)

__device__ float d_w3j111[27];
__device__ float d_w3j121[45];

// ---------------------------------------------------------------------------
// Parallel fp32 Wigner-3j init (one element per thread) — unchanged from R2.
// ---------------------------------------------------------------------------
struct CF { float r, i; };
__device__ __forceinline__ CF cmulf(CF a, CF b) {
    CF c; c.r = a.r*b.r - a.i*b.i; c.i = a.r*b.i + a.i*b.r; return c;
}

__device__ void change_basis_f(int l, CF* q) {
    int n = 2*l + 1;
    for (int a = 0; a < n*n; a++) { q[a].r = 0.f; q[a].i = 0.f; }
    const float rs2 = 0.70710678118654752f;
    for (int m = -l; m < 0; m++) {
        q[(l+m)*n + (l - m)].r =  rs2;
        q[(l+m)*n + (l + m)].i = -rs2;
    }
    q[l*n + l].r = 1.f;
    for (int m = 1; m <= l; m++) {
        float s = (m & 1) ? -1.f : 1.f;
        q[(l+m)*n + (l+m)].r = s * rs2;
        q[(l+m)*n + (l-m)].i = s * rs2;
    }
    CF ph;
    switch (l & 3) {
        case 0: ph.r = 1;  ph.i = 0;  break;
        case 1: ph.r = 0;  ph.i = -1; break;
        case 2: ph.r = -1; ph.i = 0;  break;
        default: ph.r = 0; ph.i = 1;  break;
    }
    for (int a = 0; a < n*n; a++) q[a] = cmulf(q[a], ph);
}

__device__ float cg_f(int j1, int j2, int j3, int m1, int m2, int m3,
                      const float* ft) {
    int vmin = -j1 + j2 + m3;
    if (-j1 + m1 > vmin) vmin = -j1 + m1;
    if (0 > vmin) vmin = 0;
    int vmax = j2 + j3 + m1;
    if (j3 - j1 + j2 < vmax) vmax = j3 - j1 + j2;
    if (j3 + m3 < vmax) vmax = j3 + m3;
    float C = sqrtf((2.f*j3 + 1.f) * ft[j3+j1-j2] * ft[j3-j1+j2] * ft[j1+j2-j3]
                    * ft[j3+m3] * ft[j3-m3]
                    / (ft[j1+j2+j3+1] * ft[j1-m1] * ft[j1+m1]
                       * ft[j2-m2] * ft[j2+m2]));
    float S = 0.f;
    for (int v = vmin; v <= vmax; v++) {
        float sgn = ((v + j2 + m2) & 1) ? -1.f : 1.f;
        S += sgn * ft[j2+j3+m1-v] * ft[j1-m1+v]
             / (ft[v] * ft[j3-j1+j2-v] * ft[j3+m3-v] * ft[v+j1-j2-m3]);
    }
    return C * S;
}

__device__ float w3j_elem(int l1, int l2, int l3, int j, int l, int m,
                          const float* ft) {
    int n1 = 2*l1+1, n2 = 2*l2+1, n3 = 2*l3+1;
    CF Q1[25], Q2[25], Q3[25];
    change_basis_f(l1, Q1);
    change_basis_f(l2, Q2);
    change_basis_f(l3, Q3);
    float acc = 0.f;
    for (int i = 0; i < n1; i++) {
        for (int k = 0; k < n2; k++) {
            int m3v = (i - l1) + (k - l2);
            if (m3v < -l3 || m3v > l3) continue;
            int nn = l3 + m3v;
            float cgv = cg_f(l1, l2, l3, i - l1, k - l2, m3v, ft);
            CF t = cmulf(Q1[i*n1 + j], Q2[k*n2 + l]);
            CF q3c; q3c.r = Q3[nn*n3 + m].r; q3c.i = -Q3[nn*n3 + m].i;
            t = cmulf(t, q3c);
            acc += t.r * cgv;
        }
    }
    return acc;
}

__global__ void init_w3j_kernel() {
    __shared__ float s111[27], s121[45];
    __shared__ float inv111, inv121;
    int tid = threadIdx.x;
    float ft[8];
    ft[0] = 1.f;
    for (int k = 1; k < 8; k++) ft[k] = ft[k-1] * (float)k;

    if (tid < 27) {
        int j = tid / 9, rem = tid % 9, l = rem / 3, m = rem % 3;
        s111[tid] = w3j_elem(1, 1, 1, j, l, m, ft);
    } else if (tid >= 32 && tid < 77) {
        int idx = tid - 32;
        int j = idx / 15, rem = idx % 15, l = rem / 3, m = rem % 3;
        s121[idx] = w3j_elem(1, 2, 1, j, l, m, ft);
    }
    __syncthreads();
    if (tid == 0) {
        float s = 0.f;
        for (int a = 0; a < 27; a++) s += s111[a] * s111[a];
        inv111 = rsqrtf(s);
    }
    if (tid == 1) {
        float s = 0.f;
        for (int a = 0; a < 45; a++) s += s121[a] * s121[a];
        inv121 = rsqrtf(s);
    }
    __syncthreads();
    if (tid < 27) d_w3j111[tid] = s111[tid] * inv111;
    if (tid >= 32 && tid < 77) d_w3j121[tid - 32] = s121[tid - 32] * inv121;
}

// ---------------------------------------------------------------------------
__device__ __forceinline__ uint32_t smem_u32(const void* p) {
    uint32_t a;
    asm("{ .reg .u64 t; cvta.to.shared.u64 t, %1; cvt.u32.u64 %0, t; }"
        : "=r"(a) : "l"(p));
    return a;
}

struct __align__(16) StageBuf {
    float sw[2][WTOT];
    float sx1[2][XW];
};

struct __align__(128) SmemLayout {
    StageBuf st[STAGES];            // 3 x 58272 B
    float sx2[2][12];
    float d110[2][10], d213[2][10];
    float c112[2][30], c12[2][30], c211[2][30], c22[2][30];
    float sj1[27], sj2[45];
    uint64_t mbar[STAGES];
};

__device__ __forceinline__ void issue_stage_tma(
    SmemLayout* S, int s, const float* w, const float* x1, size_t pair)
{
    uint32_t mb = smem_u32(&S->mbar[s]);
    asm volatile("fence.proxy.async.shared::cta;" ::: "memory");
    asm volatile("mbarrier.arrive.expect_tx.shared.b64 _, [%0], %1;"
                 :: "r"(mb), "r"((uint32_t)STAGE_BYTES) : "memory");
    asm volatile(
        "cp.async.bulk.shared::cluster.global.mbarrier::complete_tx::bytes "
        "[%0], [%1], %2, [%3];"
        :: "r"(smem_u32(S->st[s].sw)), "l"(w + pair * (2*WTOT)),
           "r"((uint32_t)STAGE_W_BYTES), "r"(mb) : "memory");
    asm volatile(
        "cp.async.bulk.shared::cluster.global.mbarrier::complete_tx::bytes "
        "[%0], [%1], %2, [%3];"
        :: "r"(smem_u32(S->st[s].sx1)), "l"(x1 + pair * (2*XW)),
           "r"((uint32_t)STAGE_X1_BYTES), "r"(mb) : "memory");
}

__device__ __forceinline__ void mbar_wait(uint32_t mb, uint32_t parity) {
    uint32_t done;
    do {
        asm volatile(
            "{\n .reg .pred p;\n"
            " mbarrier.try_wait.parity.acquire.cta.shared::cta.b64 p, [%1], %2, 0x989680;\n"
            " selp.b32 %0, 1, 0, p;\n}"
            : "=r"(done) : "r"(mb), "r"(parity) : "memory");
    } while (!done);
}

__global__ __launch_bounds__(320, 1) void tp_kernel(
    const float* __restrict__ x1,
    const float* __restrict__ x2,
    const float* __restrict__ w,
    float* __restrict__ out,
    int npairs)
{
    extern __shared__ __align__(128) char smem_raw[];
    SmemLayout* S = reinterpret_cast<SmemLayout*>(smem_raw);

    const int tid  = threadIdx.x;
    const int half = tid / 160;
    const int lt   = tid - half * 160;
    const int G    = gridDim.x;
    const int b    = blockIdx.x;
    const int cnt  = (npairs - b + G - 1) / G;   // iterations for this block

    // ---- Prologue: tid0 inits mbars and issues first STAGES copies ----
    if (tid == 0) {
        #pragma unroll
        for (int s = 0; s < STAGES; s++) {
            asm volatile("mbarrier.init.shared.b64 [%0], %1;"
                         :: "r"(smem_u32(&S->mbar[s])), "r"(1) : "memory");
        }
        for (int k = 0; k < STAGES; k++) {
            if (k < cnt) issue_stage_tma(S, k, w, x1, (size_t)b + (size_t)k * G);
        }
    }

    // Wigner tensors to shared (once)
    if (tid >= 128 && tid < 155)      S->sj1[tid - 128] = d_w3j111[tid - 128];
    else if (tid >= 160 && tid < 205) S->sj2[tid - 160] = d_w3j121[tid - 160];

    // x2 prefetch lanes: threads 256..273 handle the 18 floats of a pair
    const bool x2lane = (tid >= 256 && tid < 274);
    const int  x2r = (tid - 256) / 9, x2o = (tid - 256) % 9;
    float x2reg = 0.f;
    if (x2lane && cnt > 0)
        x2reg = x2[((size_t)b * 2 + x2r) * 9 + x2o];

    // ---- Hoisted per-thread constant indices ----
    // aux phase (lt-based):
    const int a_t   = (lt < 20) ? lt : (lt - 20) ;           // raw
    // main phase:
    int m_case, m_wI = 0, m_k = 0;
    if (lt < 48)       { m_case = 0; m_wI = lt; }
    else if (lt < 78)  { m_case = 1; m_wI = (lt-48)/3; m_k = (lt-48)%3; }
    else if (lt < 108) { m_case = 2; m_wI = (lt-78)/3; m_k = (lt-78)%3; }
    else if (lt < 156) { m_case = 3; m_wI = lt - 108; }
    else               { m_case = 4; }

    const float NORM_0E = 0.13130643285972254f;  // sqrt(1/58)
    const float NORM_1O = 0.19611613513818404f;  // sqrt(3/78)
    const float NORM_1E = 0.19611613513818404f;
    const float NORM_0O = 0.13130643285972254f;
    const float RS3     = 0.57735026918962576f;

    __syncthreads();   // mbar init + sj visible

    int s = 0;
    uint32_t parity = 0;
    size_t p = (size_t)b;

    for (int it = 0; it < cnt; ++it, p += G) {
        mbar_wait(smem_u32(&S->mbar[s]), parity);

        // publish this iteration's x2 from registers
        if (x2lane) S->sx2[x2r][x2o] = x2reg;
        __syncthreads();

        const StageBuf* st = &S->st[s];
        const float* px1 = st->sx1[half];
        const float* px2 = S->sx2[half];

        // ---- Aux coefficients ----
        if (lt < 10) {
            float v = 0.f;
            #pragma unroll
            for (int i = 0; i < 3; i++) v += px1[48 + lt*3 + i] * px2[1 + i];
            S->d110[half][lt] = v;
        } else if (lt < 20) {
            int u = lt - 10; float v = 0.f;
            #pragma unroll
            for (int i = 0; i < 3; i++) v += px1[78 + u*3 + i] * px2[1 + i];
            S->d213[half][u] = v;
        } else if (lt < 50) {
            int t = lt - 20, u = t/3, k = t%3; float v = 0.f;
            #pragma unroll
            for (int i = 0; i < 3; i++)
                #pragma unroll
                for (int j = 0; j < 3; j++)
                    v += px1[48 + u*3 + i] * px2[1 + j] * S->sj1[i*9 + j*3 + k];
            S->c112[half][t] = v;
        } else if (lt < 80) {
            int t = lt - 50, u = t/3, k = t%3; float v = 0.f;
            #pragma unroll
            for (int i = 0; i < 3; i++)
                #pragma unroll
                for (int j = 0; j < 5; j++)
                    v += px1[48 + u*3 + i] * px2[4 + j] * S->sj2[i*15 + j*3 + k];
            S->c12[half][t] = v;
        } else if (lt < 110) {
            int t = lt - 80, u = t/3, k = t%3; float v = 0.f;
            #pragma unroll
            for (int i = 0; i < 3; i++)
                #pragma unroll
                for (int j = 0; j < 3; j++)
                    v += px1[78 + u*3 + i] * px2[1 + j] * S->sj1[i*9 + j*3 + k];
            S->c211[half][t] = v;
        } else if (lt < 140) {
            int t = lt - 110, u = t/3, k = t%3; float v = 0.f;
            #pragma unroll
            for (int i = 0; i < 3; i++)
                #pragma unroll
                for (int j = 0; j < 5; j++)
                    v += px1[78 + u*3 + i] * px2[4 + j] * S->sj2[i*15 + j*3 + k];
            S->c22[half][t] = v;
        }

        // prefetch next iteration's x2 into registers (latency hidden by compute)
        if (x2lane && it + 1 < cnt)
            x2reg = x2[((p + G) * 2 + x2r) * 9 + x2o];

        __syncthreads();

        // ---- Main compute: one thread per output element ----
        const float* sw = st->sw[half];
        float* orow = out + (p * 2 + half) * XW;

        if (m_case == 0) {
            float a = 0.f;
            #pragma unroll 8
            for (int u = 0; u < 48; u++) a += px1[u] * sw[u*48 + m_wI];
            float bb = 0.f;
            #pragma unroll
            for (int u = 0; u < 10; u++) bb += S->d110[half][u] * sw[2884 + u*48 + m_wI];
            orow[lt] = NORM_0E * (a * px2[0] + RS3 * bb);
        } else if (m_case == 1) {
            float t01 = 0.f;
            #pragma unroll 8
            for (int u = 0; u < 48; u++) t01 += px1[u] * sw[2304 + u*10 + m_wI];
            float a10 = 0.f, a12 = 0.f, a211 = 0.f;
            #pragma unroll
            for (int u = 0; u < 10; u++) {
                a10  += px1[48 + u*3 + m_k]      * sw[2784 + u*10 + m_wI];
                a12  += S->c12[half][u*3 + m_k]  * sw[3464 + u*10 + m_wI];
                a211 += S->c211[half][u*3 + m_k] * sw[3664 + u*10 + m_wI];
            }
            orow[lt] = NORM_1O * (RS3 * (t01 * px2[1 + m_k] + px2[0] * a10) + a12 + a211);
        } else if (m_case == 2) {
            float t31 = 0.f;
            #pragma unroll 8
            for (int u = 0; u < 48; u++) t31 += px1[108 + u] * sw[6648 + u*10 + m_wI];
            float a112 = 0.f, a20 = 0.f, a22 = 0.f;
            #pragma unroll
            for (int u = 0; u < 10; u++) {
                a112 += S->c112[half][u*3 + m_k] * sw[3364 + u*10 + m_wI];
                a20  += px1[78 + u*3 + m_k]      * sw[3564 + u*10 + m_wI];
                a22  += S->c22[half][u*3 + m_k]  * sw[4244 + u*10 + m_wI];
            }
            orow[lt] = NORM_1E * (a112 + RS3 * (px2[0] * a20 + t31 * px2[1 + m_k]) + a22);
        } else if (m_case == 3) {
            float a = 0.f;
            #pragma unroll
            for (int u = 0; u < 10; u++) a += S->d213[half][u] * sw[3764 + u*48 + m_wI];
            float bb = 0.f;
            #pragma unroll 8
            for (int u = 0; u < 48; u++) bb += px1[108 + u] * sw[4344 + u*48 + m_wI];
            orow[lt] = NORM_0O * (RS3 * a + bb * px2[0]);
        }

        __syncthreads();   // all reads of stage s complete

        // ---- Reissue this stage for iteration it+STAGES ----
        if (tid == 0 && it + STAGES < cnt)
            issue_stage_tma(S, s, w, x1, p + (size_t)STAGES * G);

        if (++s == STAGES) { s = 0; parity ^= 1; }
    }
}

// ---------------------------------------------------------------------------
extern "C" void kernel_launch(void* const* d_in, const int* in_sizes, int n_in,
                              void* d_out, int out_size)
{
    const float* x1 = (const float*)d_in[0];
    const float* x2 = (const float*)d_in[1];
    const float* w  = (const float*)d_in[2];
    float* out = (float*)d_out;

    int B = in_sizes[1] / 9;
    int npairs = B / 2;
    int smem_bytes = (int)sizeof(SmemLayout);

    cudaFuncSetAttribute(tp_kernel,
                         cudaFuncAttributeMaxDynamicSharedMemorySize, smem_bytes);

    init_w3j_kernel<<<1, 128>>>();
    tp_kernel<<<148, 320, smem_bytes>>>(x1, x2, w, out, npairs);
}

// round 5
// speedup vs baseline: 1.1431x; 1.1431x over previous
#include <cuda_runtime.h>
#include <math.h>
#include <stdint.h>

// ============================================================================
// TPForth: e3nn-style tensor product, B x (x1[156], x2[9], w[7128]) -> out[156]
// Persistent kernel: 148 blocks (1/SM), 512 threads, 2-stage x 3-row TMA
// pipeline. Delivery per stage (~3.3k cyc) > compute (~2.9k cyc) => DRAM-bound.
// ============================================================================

#define WTOT 7128
#define XW   156
#define STAGES 2
#define ROWS_PER_STAGE 3

// Weight sub-matrix offsets (floats within a row), shapes (U, Wd):
//  w00  @    0 (48,48)   w01  @ 2304 (48,10)   w10  @ 2784 (10,10)
//  w110 @ 2884 (10,48)   w112 @ 3364 (10,10)   w12  @ 3464 (10,10)
//  w20  @ 3564 (10,10)   w211 @ 3664 (10,10)   w213 @ 3764 (10,48)
//  w22  @ 4244 (10,10)   w30  @ 4344 (48,48)   w31  @ 6648 (48,10)

__device__ float d_w3j111[27];
__device__ float d_w3j121[45];

// ---------------------------------------------------------------------------
// Parallel fp32 Wigner-3j init (one element per thread).
// ---------------------------------------------------------------------------
struct CF { float r, i; };
__device__ __forceinline__ CF cmulf(CF a, CF b) {
    CF c; c.r = a.r*b.r - a.i*b.i; c.i = a.r*b.i + a.i*b.r; return c;
}

__device__ void change_basis_f(int l, CF* q) {
    int n = 2*l + 1;
    for (int a = 0; a < n*n; a++) { q[a].r = 0.f; q[a].i = 0.f; }
    const float rs2 = 0.70710678118654752f;
    for (int m = -l; m < 0; m++) {
        q[(l+m)*n + (l - m)].r =  rs2;
        q[(l+m)*n + (l + m)].i = -rs2;
    }
    q[l*n + l].r = 1.f;
    for (int m = 1; m <= l; m++) {
        float s = (m & 1) ? -1.f : 1.f;
        q[(l+m)*n + (l+m)].r = s * rs2;
        q[(l+m)*n + (l-m)].i = s * rs2;
    }
    CF ph;
    switch (l & 3) {
        case 0: ph.r = 1;  ph.i = 0;  break;
        case 1: ph.r = 0;  ph.i = -1; break;
        case 2: ph.r = -1; ph.i = 0;  break;
        default: ph.r = 0; ph.i = 1;  break;
    }
    for (int a = 0; a < n*n; a++) q[a] = cmulf(q[a], ph);
}

__device__ float cg_f(int j1, int j2, int j3, int m1, int m2, int m3,
                      const float* ft) {
    int vmin = -j1 + j2 + m3;
    if (-j1 + m1 > vmin) vmin = -j1 + m1;
    if (0 > vmin) vmin = 0;
    int vmax = j2 + j3 + m1;
    if (j3 - j1 + j2 < vmax) vmax = j3 - j1 + j2;
    if (j3 + m3 < vmax) vmax = j3 + m3;
    float C = sqrtf((2.f*j3 + 1.f) * ft[j3+j1-j2] * ft[j3-j1+j2] * ft[j1+j2-j3]
                    * ft[j3+m3] * ft[j3-m3]
                    / (ft[j1+j2+j3+1] * ft[j1-m1] * ft[j1+m1]
                       * ft[j2-m2] * ft[j2+m2]));
    float S = 0.f;
    for (int v = vmin; v <= vmax; v++) {
        float sgn = ((v + j2 + m2) & 1) ? -1.f : 1.f;
        S += sgn * ft[j2+j3+m1-v] * ft[j1-m1+v]
             / (ft[v] * ft[j3-j1+j2-v] * ft[j3+m3-v] * ft[v+j1-j2-m3]);
    }
    return C * S;
}

__device__ float w3j_elem(int l1, int l2, int l3, int j, int l, int m,
                          const float* ft) {
    int n1 = 2*l1+1, n2 = 2*l2+1, n3 = 2*l3+1;
    CF Q1[25], Q2[25], Q3[25];
    change_basis_f(l1, Q1);
    change_basis_f(l2, Q2);
    change_basis_f(l3, Q3);
    float acc = 0.f;
    for (int i = 0; i < n1; i++) {
        for (int k = 0; k < n2; k++) {
            int m3v = (i - l1) + (k - l2);
            if (m3v < -l3 || m3v > l3) continue;
            int nn = l3 + m3v;
            float cgv = cg_f(l1, l2, l3, i - l1, k - l2, m3v, ft);
            CF t = cmulf(Q1[i*n1 + j], Q2[k*n2 + l]);
            CF q3c; q3c.r = Q3[nn*n3 + m].r; q3c.i = -Q3[nn*n3 + m].i;
            t = cmulf(t, q3c);
            acc += t.r * cgv;
        }
    }
    return acc;
}

__global__ void init_w3j_kernel() {
    __shared__ float s111[27], s121[45];
    __shared__ float inv111, inv121;
    int tid = threadIdx.x;
    float ft[8];
    ft[0] = 1.f;
    for (int k = 1; k < 8; k++) ft[k] = ft[k-1] * (float)k;

    if (tid < 27) {
        int j = tid / 9, rem = tid % 9, l = rem / 3, m = rem % 3;
        s111[tid] = w3j_elem(1, 1, 1, j, l, m, ft);
    } else if (tid >= 32 && tid < 77) {
        int idx = tid - 32;
        int j = idx / 15, rem = idx % 15, l = rem / 3, m = rem % 3;
        s121[idx] = w3j_elem(1, 2, 1, j, l, m, ft);
    }
    __syncthreads();
    if (tid == 0) {
        float s = 0.f;
        for (int a = 0; a < 27; a++) s += s111[a] * s111[a];
        inv111 = rsqrtf(s);
    }
    if (tid == 1) {
        float s = 0.f;
        for (int a = 0; a < 45; a++) s += s121[a] * s121[a];
        inv121 = rsqrtf(s);
    }
    __syncthreads();
    if (tid < 27) d_w3j111[tid] = s111[tid] * inv111;
    if (tid >= 32 && tid < 77) d_w3j121[tid - 32] = s121[tid - 32] * inv121;
}

// ---------------------------------------------------------------------------
__device__ __forceinline__ uint32_t smem_u32(const void* p) {
    uint32_t a;
    asm("{ .reg .u64 t; cvta.to.shared.u64 t, %1; cvt.u32.u64 %0, t; }"
        : "=r"(a) : "l"(p));
    return a;
}

struct __align__(16) StageBuf {
    float sw[ROWS_PER_STAGE][WTOT];
    float sx1[ROWS_PER_STAGE][XW];
};

struct __align__(128) SmemLayout {
    StageBuf st[STAGES];                       // 2 x 87408 B
    float sx2[ROWS_PER_STAGE][12];
    float d110[ROWS_PER_STAGE][10], d213[ROWS_PER_STAGE][10];
    float c112[ROWS_PER_STAGE][30], c12[ROWS_PER_STAGE][30];
    float c211[ROWS_PER_STAGE][30], c22[ROWS_PER_STAGE][30];
    float sj1[27], sj2[45];
    uint64_t mbar[STAGES];
};

__device__ __forceinline__ void issue_stage_tma(
    SmemLayout* S, int s, const float* w, const float* x1,
    size_t row0, int nrows)
{
    uint32_t mb = smem_u32(&S->mbar[s]);
    uint32_t wb = (uint32_t)(nrows * WTOT * 4);
    uint32_t xb = (uint32_t)(nrows * XW * 4);
    asm volatile("fence.proxy.async.shared::cta;" ::: "memory");
    asm volatile("mbarrier.arrive.expect_tx.shared.b64 _, [%0], %1;"
                 :: "r"(mb), "r"(wb + xb) : "memory");
    asm volatile(
        "cp.async.bulk.shared::cluster.global.mbarrier::complete_tx::bytes "
        "[%0], [%1], %2, [%3];"
        :: "r"(smem_u32(S->st[s].sw)), "l"(w + row0 * WTOT), "r"(wb), "r"(mb)
        : "memory");
    asm volatile(
        "cp.async.bulk.shared::cluster.global.mbarrier::complete_tx::bytes "
        "[%0], [%1], %2, [%3];"
        :: "r"(smem_u32(S->st[s].sx1)), "l"(x1 + row0 * XW), "r"(xb), "r"(mb)
        : "memory");
}

__device__ __forceinline__ void mbar_wait(uint32_t mb, uint32_t parity) {
    uint32_t done;
    do {
        asm volatile(
            "{\n .reg .pred p;\n"
            " mbarrier.try_wait.parity.acquire.cta.shared::cta.b64 p, [%1], %2, 0x989680;\n"
            " selp.b32 %0, 1, 0, p;\n}"
            : "=r"(done) : "r"(mb), "r"(parity) : "memory");
    } while (!done);
}

__global__ __launch_bounds__(512, 1) void tp_kernel(
    const float* __restrict__ x1,
    const float* __restrict__ x2,
    const float* __restrict__ w,
    float* __restrict__ out,
    int nrows_total)
{
    extern __shared__ __align__(128) char smem_raw[];
    SmemLayout* S = reinterpret_cast<SmemLayout*>(smem_raw);

    const int tid = threadIdx.x;
    const int g   = tid / 160;            // row group 0..2 (3 = spare)
    const int lt  = tid - g * 160;
    const int G   = gridDim.x;
    const int b   = blockIdx.x;
    const int ntriples = (nrows_total + ROWS_PER_STAGE - 1) / ROWS_PER_STAGE;
    const int cnt = (ntriples > b) ? (ntriples - b + G - 1) / G : 0;

    // ---- Prologue ----
    if (tid == 0) {
        #pragma unroll
        for (int s = 0; s < STAGES; s++) {
            asm volatile("mbarrier.init.shared.b64 [%0], %1;"
                         :: "r"(smem_u32(&S->mbar[s])), "r"(1) : "memory");
        }
        for (int k = 0; k < STAGES && k < cnt; k++) {
            size_t tr = (size_t)b + (size_t)k * G;
            size_t r0 = tr * ROWS_PER_STAGE;
            int nr = (int)(((size_t)nrows_total - r0 < ROWS_PER_STAGE)
                           ? (nrows_total - r0) : ROWS_PER_STAGE);
            issue_stage_tma(S, k, w, x1, r0, nr);
        }
    }

    if (tid >= 128 && tid < 155)      S->sj1[tid - 128] = d_w3j111[tid - 128];
    else if (tid >= 160 && tid < 205) S->sj2[tid - 160] = d_w3j121[tid - 160];

    // x2 prefetch lanes: tid 480..506 handle 27 floats (3 rows x 9)
    const bool x2lane = (tid >= 480 && tid < 480 + 27);
    const int  x2r = (tid - 480) / 9, x2o = (tid - 480) % 9;
    float x2reg = 0.f;
    if (x2lane && cnt > 0) {
        size_t row = (size_t)b * ROWS_PER_STAGE + x2r;
        if (row < (size_t)nrows_total) x2reg = x2[row * 9 + x2o];
    }

    // Hoisted per-thread output indices
    int m_case, m_wI = 0, m_k = 0;
    if (lt < 48)       { m_case = 0; m_wI = lt; }
    else if (lt < 78)  { m_case = 1; m_wI = (lt-48)/3; m_k = (lt-48)%3; }
    else if (lt < 108) { m_case = 2; m_wI = (lt-78)/3; m_k = (lt-78)%3; }
    else if (lt < 156) { m_case = 3; m_wI = lt - 108; }
    else               { m_case = 4; }
    if (g >= ROWS_PER_STAGE) m_case = 4;

    const float NORM_0E = 0.13130643285972254f;  // sqrt(1/58)
    const float NORM_1O = 0.19611613513818404f;  // sqrt(3/78)
    const float NORM_1E = 0.19611613513818404f;
    const float NORM_0O = 0.13130643285972254f;
    const float RS3     = 0.57735026918962576f;

    __syncthreads();   // mbar init + sj visible

    int s = 0;
    uint32_t parity = 0;
    size_t tr = (size_t)b;

    for (int it = 0; it < cnt; ++it, tr += G) {
        const size_t row0 = tr * ROWS_PER_STAGE;
        const bool rowok = (g < ROWS_PER_STAGE) && (row0 + g < (size_t)nrows_total);

        mbar_wait(smem_u32(&S->mbar[s]), parity);

        if (x2lane) S->sx2[x2r][x2o] = x2reg;
        __syncthreads();

        const StageBuf* st = &S->st[s];
        const float* px1 = st->sx1[g < ROWS_PER_STAGE ? g : 0];
        const float* px2 = S->sx2[g < ROWS_PER_STAGE ? g : 0];

        // ---- Aux coefficients (per row group) ----
        if (rowok) {
            if (lt < 10) {
                float v = 0.f;
                #pragma unroll
                for (int i = 0; i < 3; i++) v += px1[48 + lt*3 + i] * px2[1 + i];
                S->d110[g][lt] = v;
            } else if (lt < 20) {
                int u = lt - 10; float v = 0.f;
                #pragma unroll
                for (int i = 0; i < 3; i++) v += px1[78 + u*3 + i] * px2[1 + i];
                S->d213[g][u] = v;
            } else if (lt < 50) {
                int t = lt - 20, u = t/3, k = t%3; float v = 0.f;
                #pragma unroll
                for (int i = 0; i < 3; i++)
                    #pragma unroll
                    for (int j = 0; j < 3; j++)
                        v += px1[48 + u*3 + i] * px2[1 + j] * S->sj1[i*9 + j*3 + k];
                S->c112[g][t] = v;
            } else if (lt < 80) {
                int t = lt - 50, u = t/3, k = t%3; float v = 0.f;
                #pragma unroll
                for (int i = 0; i < 3; i++)
                    #pragma unroll
                    for (int j = 0; j < 5; j++)
                        v += px1[48 + u*3 + i] * px2[4 + j] * S->sj2[i*15 + j*3 + k];
                S->c12[g][t] = v;
            } else if (lt < 110) {
                int t = lt - 80, u = t/3, k = t%3; float v = 0.f;
                #pragma unroll
                for (int i = 0; i < 3; i++)
                    #pragma unroll
                    for (int j = 0; j < 3; j++)
                        v += px1[78 + u*3 + i] * px2[1 + j] * S->sj1[i*9 + j*3 + k];
                S->c211[g][t] = v;
            } else if (lt < 140) {
                int t = lt - 110, u = t/3, k = t%3; float v = 0.f;
                #pragma unroll
                for (int i = 0; i < 3; i++)
                    #pragma unroll
                    for (int j = 0; j < 5; j++)
                        v += px1[78 + u*3 + i] * px2[4 + j] * S->sj2[i*15 + j*3 + k];
                S->c22[g][t] = v;
            }
        }

        // prefetch next iteration's x2
        if (x2lane && it + 1 < cnt) {
            size_t row = (tr + G) * ROWS_PER_STAGE + x2r;
            x2reg = (row < (size_t)nrows_total) ? x2[row * 9 + x2o] : 0.f;
        }

        __syncthreads();

        // ---- Main compute: one thread per output element ----
        if (rowok && m_case < 4) {
            const float* sw = st->sw[g];
            float* orow = out + (row0 + g) * XW;

            if (m_case == 0) {
                float a = 0.f;
                #pragma unroll 8
                for (int u = 0; u < 48; u++) a += px1[u] * sw[u*48 + m_wI];
                float bb = 0.f;
                #pragma unroll
                for (int u = 0; u < 10; u++) bb += S->d110[g][u] * sw[2884 + u*48 + m_wI];
                orow[lt] = NORM_0E * (a * px2[0] + RS3 * bb);
            } else if (m_case == 1) {
                float t01 = 0.f;
                #pragma unroll 8
                for (int u = 0; u < 48; u++) t01 += px1[u] * sw[2304 + u*10 + m_wI];
                float a10 = 0.f, a12 = 0.f, a211 = 0.f;
                #pragma unroll
                for (int u = 0; u < 10; u++) {
                    a10  += px1[48 + u*3 + m_k]   * sw[2784 + u*10 + m_wI];
                    a12  += S->c12[g][u*3 + m_k]  * sw[3464 + u*10 + m_wI];
                    a211 += S->c211[g][u*3 + m_k] * sw[3664 + u*10 + m_wI];
                }
                orow[lt] = NORM_1O * (RS3 * (t01 * px2[1 + m_k] + px2[0] * a10) + a12 + a211);
            } else if (m_case == 2) {
                float t31 = 0.f;
                #pragma unroll 8
                for (int u = 0; u < 48; u++) t31 += px1[108 + u] * sw[6648 + u*10 + m_wI];
                float a112 = 0.f, a20 = 0.f, a22 = 0.f;
                #pragma unroll
                for (int u = 0; u < 10; u++) {
                    a112 += S->c112[g][u*3 + m_k] * sw[3364 + u*10 + m_wI];
                    a20  += px1[78 + u*3 + m_k]   * sw[3564 + u*10 + m_wI];
                    a22  += S->c22[g][u*3 + m_k]  * sw[4244 + u*10 + m_wI];
                }
                orow[lt] = NORM_1E * (a112 + RS3 * (px2[0] * a20 + t31 * px2[1 + m_k]) + a22);
            } else {
                float a = 0.f;
                #pragma unroll
                for (int u = 0; u < 10; u++) a += S->d213[g][u] * sw[3764 + u*48 + m_wI];
                float bb = 0.f;
                #pragma unroll 8
                for (int u = 0; u < 48; u++) bb += px1[108 + u] * sw[4344 + u*48 + m_wI];
                orow[lt] = NORM_0O * (RS3 * a + bb * px2[0]);
            }
        }

        __syncthreads();   // all reads of stage s done

        // ---- Reissue this stage for iteration it+STAGES ----
        if (tid == 0 && it + STAGES < cnt) {
            size_t ntr = tr + (size_t)STAGES * G;
            size_t r0 = ntr * ROWS_PER_STAGE;
            int nr = (int)(((size_t)nrows_total - r0 < ROWS_PER_STAGE)
                           ? (nrows_total - r0) : ROWS_PER_STAGE);
            issue_stage_tma(S, s, w, x1, r0, nr);
        }

        if (++s == STAGES) { s = 0; parity ^= 1; }
    }
}

// ---------------------------------------------------------------------------
extern "C" void kernel_launch(void* const* d_in, const int* in_sizes, int n_in,
                              void* d_out, int out_size)
{
    const float* x1 = (const float*)d_in[0];
    const float* x2 = (const float*)d_in[1];
    const float* w  = (const float*)d_in[2];
    float* out = (float*)d_out;

    int B = in_sizes[1] / 9;
    int smem_bytes = (int)sizeof(SmemLayout);

    cudaFuncSetAttribute(tp_kernel,
                         cudaFuncAttributeMaxDynamicSharedMemorySize, smem_bytes);

    init_w3j_kernel<<<1, 128>>>();
    tp_kernel<<<148, 512, smem_bytes>>>(x1, x2, w, out, B);
}

// round 6
// speedup vs baseline: 1.1545x; 1.0100x over previous
#include <cuda_runtime.h>
#include <math.h>
#include <stdint.h>

// ============================================================================
// TPForth: e3nn-style tensor product, B x (x1[156], x2[9], w[7128]) -> out[156]
// Persistent kernel: 148 blocks (1/SM), 640 threads = 2 independent compute
// teams x 320. 3-stage x 2-row TMA ring; stage i%3, team i%2, phase (i/3)&1.
// Team that consumes a stage reissues it for i+3. DRAM-bound period.
// ============================================================================

#define WTOT 7128
#define XW   156
#define STAGES 3
#define ROWS_PER_STAGE 2
#define TEAM_THREADS 320

// Weight sub-matrix offsets (floats within a row), shapes (U, Wd):
//  w00  @    0 (48,48)   w01  @ 2304 (48,10)   w10  @ 2784 (10,10)
//  w110 @ 2884 (10,48)   w112 @ 3364 (10,10)   w12  @ 3464 (10,10)
//  w20  @ 3564 (10,10)   w211 @ 3664 (10,10)   w213 @ 3764 (10,48)
//  w22  @ 4244 (10,10)   w30  @ 4344 (48,48)   w31  @ 6648 (48,10)

__device__ float d_w3j111[27];
__device__ float d_w3j121[45];

// ---------------------------------------------------------------------------
// Parallel fp32 Wigner-3j init (one element per thread).
// ---------------------------------------------------------------------------
struct CF { float r, i; };
__device__ __forceinline__ CF cmulf(CF a, CF b) {
    CF c; c.r = a.r*b.r - a.i*b.i; c.i = a.r*b.i + a.i*b.r; return c;
}

__device__ void change_basis_f(int l, CF* q) {
    int n = 2*l + 1;
    for (int a = 0; a < n*n; a++) { q[a].r = 0.f; q[a].i = 0.f; }
    const float rs2 = 0.70710678118654752f;
    for (int m = -l; m < 0; m++) {
        q[(l+m)*n + (l - m)].r =  rs2;
        q[(l+m)*n + (l + m)].i = -rs2;
    }
    q[l*n + l].r = 1.f;
    for (int m = 1; m <= l; m++) {
        float s = (m & 1) ? -1.f : 1.f;
        q[(l+m)*n + (l+m)].r = s * rs2;
        q[(l+m)*n + (l-m)].i = s * rs2;
    }
    CF ph;
    switch (l & 3) {
        case 0: ph.r = 1;  ph.i = 0;  break;
        case 1: ph.r = 0;  ph.i = -1; break;
        case 2: ph.r = -1; ph.i = 0;  break;
        default: ph.r = 0; ph.i = 1;  break;
    }
    for (int a = 0; a < n*n; a++) q[a] = cmulf(q[a], ph);
}

__device__ float cg_f(int j1, int j2, int j3, int m1, int m2, int m3,
                      const float* ft) {
    int vmin = -j1 + j2 + m3;
    if (-j1 + m1 > vmin) vmin = -j1 + m1;
    if (0 > vmin) vmin = 0;
    int vmax = j2 + j3 + m1;
    if (j3 - j1 + j2 < vmax) vmax = j3 - j1 + j2;
    if (j3 + m3 < vmax) vmax = j3 + m3;
    float C = sqrtf((2.f*j3 + 1.f) * ft[j3+j1-j2] * ft[j3-j1+j2] * ft[j1+j2-j3]
                    * ft[j3+m3] * ft[j3-m3]
                    / (ft[j1+j2+j3+1] * ft[j1-m1] * ft[j1+m1]
                       * ft[j2-m2] * ft[j2+m2]));
    float S = 0.f;
    for (int v = vmin; v <= vmax; v++) {
        float sgn = ((v + j2 + m2) & 1) ? -1.f : 1.f;
        S += sgn * ft[j2+j3+m1-v] * ft[j1-m1+v]
             / (ft[v] * ft[j3-j1+j2-v] * ft[j3+m3-v] * ft[v+j1-j2-m3]);
    }
    return C * S;
}

__device__ float w3j_elem(int l1, int l2, int l3, int j, int l, int m,
                          const float* ft) {
    int n1 = 2*l1+1, n2 = 2*l2+1, n3 = 2*l3+1;
    CF Q1[25], Q2[25], Q3[25];
    change_basis_f(l1, Q1);
    change_basis_f(l2, Q2);
    change_basis_f(l3, Q3);
    float acc = 0.f;
    for (int i = 0; i < n1; i++) {
        for (int k = 0; k < n2; k++) {
            int m3v = (i - l1) + (k - l2);
            if (m3v < -l3 || m3v > l3) continue;
            int nn = l3 + m3v;
            float cgv = cg_f(l1, l2, l3, i - l1, k - l2, m3v, ft);
            CF t = cmulf(Q1[i*n1 + j], Q2[k*n2 + l]);
            CF q3c; q3c.r = Q3[nn*n3 + m].r; q3c.i = -Q3[nn*n3 + m].i;
            t = cmulf(t, q3c);
            acc += t.r * cgv;
        }
    }
    return acc;
}

__global__ void init_w3j_kernel() {
    __shared__ float s111[27], s121[45];
    __shared__ float inv111, inv121;
    int tid = threadIdx.x;
    float ft[8];
    ft[0] = 1.f;
    for (int k = 1; k < 8; k++) ft[k] = ft[k-1] * (float)k;

    if (tid < 27) {
        int j = tid / 9, rem = tid % 9, l = rem / 3, m = rem % 3;
        s111[tid] = w3j_elem(1, 1, 1, j, l, m, ft);
    } else if (tid >= 32 && tid < 77) {
        int idx = tid - 32;
        int j = idx / 15, rem = idx % 15, l = rem / 3, m = rem % 3;
        s121[idx] = w3j_elem(1, 2, 1, j, l, m, ft);
    }
    __syncthreads();
    if (tid == 0) {
        float s = 0.f;
        for (int a = 0; a < 27; a++) s += s111[a] * s111[a];
        inv111 = rsqrtf(s);
    }
    if (tid == 1) {
        float s = 0.f;
        for (int a = 0; a < 45; a++) s += s121[a] * s121[a];
        inv121 = rsqrtf(s);
    }
    __syncthreads();
    if (tid < 27) d_w3j111[tid] = s111[tid] * inv111;
    if (tid >= 32 && tid < 77) d_w3j121[tid - 32] = s121[tid - 32] * inv121;
}

// ---------------------------------------------------------------------------
__device__ __forceinline__ uint32_t smem_u32(const void* p) {
    uint32_t a;
    asm("{ .reg .u64 t; cvta.to.shared.u64 t, %1; cvt.u32.u64 %0, t; }"
        : "=r"(a) : "l"(p));
    return a;
}

struct __align__(16) StageBuf {
    float sw[ROWS_PER_STAGE][WTOT];
    float sx1[ROWS_PER_STAGE][XW];
};

struct __align__(16) TeamAux {
    float sx2[2][12];
    float d110[2][10], d213[2][10];
    float c112[2][30], c12[2][30], c211[2][30], c22[2][30];
};

struct __align__(128) SmemLayout {
    StageBuf st[STAGES];           // 3 x 58272 B
    TeamAux  aux[2];
    float sj1[27], sj2[45];
    uint64_t mbar[STAGES];
};

__device__ __forceinline__ void issue_stage_tma(
    SmemLayout* S, int s, const float* w, const float* x1, size_t pair)
{
    uint32_t mb = smem_u32(&S->mbar[s]);
    const uint32_t wb = (uint32_t)(ROWS_PER_STAGE * WTOT * 4);
    const uint32_t xb = (uint32_t)(ROWS_PER_STAGE * XW * 4);
    asm volatile("fence.proxy.async.shared::cta;" ::: "memory");
    asm volatile("mbarrier.arrive.expect_tx.shared.b64 _, [%0], %1;"
                 :: "r"(mb), "r"(wb + xb) : "memory");
    asm volatile(
        "cp.async.bulk.shared::cluster.global.mbarrier::complete_tx::bytes "
        "[%0], [%1], %2, [%3];"
        :: "r"(smem_u32(S->st[s].sw)), "l"(w + pair * (ROWS_PER_STAGE*WTOT)),
           "r"(wb), "r"(mb) : "memory");
    asm volatile(
        "cp.async.bulk.shared::cluster.global.mbarrier::complete_tx::bytes "
        "[%0], [%1], %2, [%3];"
        :: "r"(smem_u32(S->st[s].sx1)), "l"(x1 + pair * (ROWS_PER_STAGE*XW)),
           "r"(xb), "r"(mb) : "memory");
}

__device__ __forceinline__ void mbar_wait(uint32_t mb, uint32_t parity) {
    uint32_t done;
    do {
        asm volatile(
            "{\n .reg .pred p;\n"
            " mbarrier.try_wait.parity.acquire.cta.shared::cta.b64 p, [%1], %2, 0x989680;\n"
            " selp.b32 %0, 1, 0, p;\n}"
            : "=r"(done) : "r"(mb), "r"(parity) : "memory");
    } while (!done);
}

__device__ __forceinline__ void team_bar(int team) {
    asm volatile("bar.sync %0, %1;" :: "r"(team + 1), "r"(TEAM_THREADS)
                 : "memory");
}

__global__ __launch_bounds__(640, 1) void tp_kernel(
    const float* __restrict__ x1,
    const float* __restrict__ x2,
    const float* __restrict__ w,
    float* __restrict__ out,
    int npairs)
{
    extern __shared__ __align__(128) char smem_raw[];
    SmemLayout* S = reinterpret_cast<SmemLayout*>(smem_raw);

    const int tid  = threadIdx.x;
    const int team = tid / TEAM_THREADS;     // 0 or 1
    const int tt   = tid - team * TEAM_THREADS;
    const int half = tt / 160;               // row within pair
    const int lt   = tt - half * 160;
    const int G    = gridDim.x;
    const int b    = blockIdx.x;
    const int cnt  = (npairs > b) ? (npairs - b + G - 1) / G : 0;

    // ---- Prologue: init mbars, fill stages 0..2 ----
    if (tid == 0) {
        #pragma unroll
        for (int s = 0; s < STAGES; s++) {
            asm volatile("mbarrier.init.shared.b64 [%0], %1;"
                         :: "r"(smem_u32(&S->mbar[s])), "r"(1) : "memory");
        }
        for (int k = 0; k < STAGES && k < cnt; k++)
            issue_stage_tma(S, k, w, x1, (size_t)b + (size_t)k * G);
    }
    if (tid >= 128 && tid < 155)      S->sj1[tid - 128] = d_w3j111[tid - 128];
    else if (tid >= 160 && tid < 205) S->sj2[tid - 160] = d_w3j121[tid - 160];

    // x2 lanes: team-local threads 256..273 load the pair's 18 x2 floats
    const bool x2lane = (tt >= 256 && tt < 274);
    const int  x2r = (tt - 256) / 9, x2o = (tt - 256) % 9;

    // Hoisted per-thread output indices
    int m_case, m_wI = 0, m_k = 0;
    if (lt < 48)       { m_case = 0; m_wI = lt; }
    else if (lt < 78)  { m_case = 1; m_wI = (lt-48)/3; m_k = (lt-48)%3; }
    else if (lt < 108) { m_case = 2; m_wI = (lt-78)/3; m_k = (lt-78)%3; }
    else if (lt < 156) { m_case = 3; m_wI = lt - 108; }
    else               { m_case = 4; }

    const float NORM_0E = 0.13130643285972254f;  // sqrt(1/58)
    const float NORM_1O = 0.19611613513818404f;  // sqrt(3/78)
    const float NORM_1E = 0.19611613513818404f;
    const float NORM_0O = 0.13130643285972254f;
    const float RS3     = 0.57735026918962576f;

    TeamAux* A = &S->aux[team];

    __syncthreads();   // mbar init + sj visible to both teams

    // ---- Team loop: team handles iterations i = team, team+2, ... ----
    for (int i = team; i < cnt; i += 2) {
        const int s = i % 3;
        const uint32_t parity = (uint32_t)((i / 3) & 1);
        const size_t p = (size_t)b + (size_t)i * G;

        // issue x2 LDG before the wait (latency overlaps TMA delivery)
        float x2reg = 0.f;
        if (x2lane) x2reg = x2[(p * 2 + x2r) * 9 + x2o];

        mbar_wait(smem_u32(&S->mbar[s]), parity);

        if (x2lane) A->sx2[x2r][x2o] = x2reg;
        team_bar(team);

        const StageBuf* st = &S->st[s];
        const float* px1 = st->sx1[half];
        const float* px2 = A->sx2[half];

        // ---- Aux coefficients ----
        if (lt < 10) {
            float v = 0.f;
            #pragma unroll
            for (int q = 0; q < 3; q++) v += px1[48 + lt*3 + q] * px2[1 + q];
            A->d110[half][lt] = v;
        } else if (lt < 20) {
            int u = lt - 10; float v = 0.f;
            #pragma unroll
            for (int q = 0; q < 3; q++) v += px1[78 + u*3 + q] * px2[1 + q];
            A->d213[half][u] = v;
        } else if (lt < 50) {
            int t = lt - 20, u = t/3, k = t%3; float v = 0.f;
            #pragma unroll
            for (int q = 0; q < 3; q++)
                #pragma unroll
                for (int j = 0; j < 3; j++)
                    v += px1[48 + u*3 + q] * px2[1 + j] * S->sj1[q*9 + j*3 + k];
            A->c112[half][t] = v;
        } else if (lt < 80) {
            int t = lt - 50, u = t/3, k = t%3; float v = 0.f;
            #pragma unroll
            for (int q = 0; q < 3; q++)
                #pragma unroll
                for (int j = 0; j < 5; j++)
                    v += px1[48 + u*3 + q] * px2[4 + j] * S->sj2[q*15 + j*3 + k];
            A->c12[half][t] = v;
        } else if (lt < 110) {
            int t = lt - 80, u = t/3, k = t%3; float v = 0.f;
            #pragma unroll
            for (int q = 0; q < 3; q++)
                #pragma unroll
                for (int j = 0; j < 3; j++)
                    v += px1[78 + u*3 + q] * px2[1 + j] * S->sj1[q*9 + j*3 + k];
            A->c211[half][t] = v;
        } else if (lt < 140) {
            int t = lt - 110, u = t/3, k = t%3; float v = 0.f;
            #pragma unroll
            for (int q = 0; q < 3; q++)
                #pragma unroll
                for (int j = 0; j < 5; j++)
                    v += px1[78 + u*3 + q] * px2[4 + j] * S->sj2[q*15 + j*3 + k];
            A->c22[half][t] = v;
        }
        team_bar(team);

        // ---- Main compute: one thread per output element ----
        if (m_case < 4) {
            const float* sw = st->sw[half];
            float* orow = out + (p * 2 + half) * XW;

            if (m_case == 0) {
                float a = 0.f;
                #pragma unroll 8
                for (int u = 0; u < 48; u++) a += px1[u] * sw[u*48 + m_wI];
                float bb = 0.f;
                #pragma unroll
                for (int u = 0; u < 10; u++) bb += A->d110[half][u] * sw[2884 + u*48 + m_wI];
                orow[lt] = NORM_0E * (a * px2[0] + RS3 * bb);
            } else if (m_case == 1) {
                float t01 = 0.f;
                #pragma unroll 8
                for (int u = 0; u < 48; u++) t01 += px1[u] * sw[2304 + u*10 + m_wI];
                float a10 = 0.f, a12 = 0.f, a211 = 0.f;
                #pragma unroll
                for (int u = 0; u < 10; u++) {
                    a10  += px1[48 + u*3 + m_k]      * sw[2784 + u*10 + m_wI];
                    a12  += A->c12[half][u*3 + m_k]  * sw[3464 + u*10 + m_wI];
                    a211 += A->c211[half][u*3 + m_k] * sw[3664 + u*10 + m_wI];
                }
                orow[lt] = NORM_1O * (RS3 * (t01 * px2[1 + m_k] + px2[0] * a10) + a12 + a211);
            } else if (m_case == 2) {
                float t31 = 0.f;
                #pragma unroll 8
                for (int u = 0; u < 48; u++) t31 += px1[108 + u] * sw[6648 + u*10 + m_wI];
                float a112 = 0.f, a20 = 0.f, a22 = 0.f;
                #pragma unroll
                for (int u = 0; u < 10; u++) {
                    a112 += A->c112[half][u*3 + m_k] * sw[3364 + u*10 + m_wI];
                    a20  += px1[78 + u*3 + m_k]      * sw[3564 + u*10 + m_wI];
                    a22  += A->c22[half][u*3 + m_k]  * sw[4244 + u*10 + m_wI];
                }
                orow[lt] = NORM_1E * (a112 + RS3 * (px2[0] * a20 + t31 * px2[1 + m_k]) + a22);
            } else {
                float a = 0.f;
                #pragma unroll
                for (int u = 0; u < 10; u++) a += A->d213[half][u] * sw[3764 + u*48 + m_wI];
                float bb = 0.f;
                #pragma unroll 8
                for (int u = 0; u < 48; u++) bb += px1[108 + u] * sw[4344 + u*48 + m_wI];
                orow[lt] = NORM_0O * (RS3 * a + bb * px2[0]);
            }
        }

        team_bar(team);   // this team done reading stage s

        // ---- Reissue stage s for iteration i+3 (consumer reissues) ----
        if (tt == 0 && i + 3 < cnt)
            issue_stage_tma(S, s, w, x1, (size_t)b + (size_t)(i + 3) * G);
    }
}

// ---------------------------------------------------------------------------
extern "C" void kernel_launch(void* const* d_in, const int* in_sizes, int n_in,
                              void* d_out, int out_size)
{
    const float* x1 = (const float*)d_in[0];
    const float* x2 = (const float*)d_in[1];
    const float* w  = (const float*)d_in[2];
    float* out = (float*)d_out;

    int B = in_sizes[1] / 9;
    int npairs = B / 2;
    int smem_bytes = (int)sizeof(SmemLayout);

    cudaFuncSetAttribute(tp_kernel,
                         cudaFuncAttributeMaxDynamicSharedMemorySize, smem_bytes);

    init_w3j_kernel<<<1, 128>>>();
    tp_kernel<<<148, 640, smem_bytes>>>(x1, x2, w, out, npairs);
}